// round 14
// baseline (speedup 1.0000x reference)
#include <cuda_runtime.h>

#define D 128
#define H 128
#define LN_EPS 1e-3f

// ---------------- scratch (device globals; no allocation) ----------------
__device__ float    g_dAT[128 * 1024];    // A^T : [h][pos_row]
__device__ float    g_dBT[128 * 512];     // B^T : [h][col_row]
__device__ float4   g_rStat[1024];        // {sum, sumsq, dot_g, 0}
__device__ float4   g_cStat[512];
__device__ float    g_rowSum[1024];
__device__ float    g_segSum[64 * 512];   // [n_seq][n_col]
__device__ int      g_segId[1024];
__device__ float    g_G, g_C0;
__device__ unsigned g_cnt;                // zero-init; self-resetting
__device__ unsigned g_flag;
__device__ unsigned g_sense[1024];

__device__ __forceinline__ void grid_barrier(int nblk) {
    __syncthreads();
    if (threadIdx.x == 0) {
        unsigned s = g_sense[blockIdx.x] ^ 1u;
        g_sense[blockIdx.x] = s;
        __threadfence();
        unsigned old = atomicAdd(&g_cnt, 1u);
        if (old == (unsigned)(nblk - 1)) {
            g_cnt = 0u;
            __threadfence();
            *(volatile unsigned*)&g_flag = s;
        } else {
            while (*(volatile unsigned*)&g_flag != s) { }
        }
        __threadfence();
    }
    __syncthreads();
}

__global__ void __launch_bounds__(256, 4)
k_fused(const float* __restrict__ seqf, const float* __restrict__ colf,
        const float* __restrict__ Ws, const float* __restrict__ bs,
        const float* __restrict__ Wc, const float* __restrict__ bc,
        const float* __restrict__ Wm, const float* __restrict__ bm,
        const float* __restrict__ gamma, const float* __restrict__ beta,
        const float* __restrict__ Wo, const float* __restrict__ bo,
        const int* __restrict__ lens,
        float* __restrict__ E,
        int n_pos, int n_col, int n_seq, int nblk) {
    const int tid = threadIdx.x;
    const int bid = blockIdx.x;

    // pool: prep uses sW[64][128] (8192) + fbuf(512) + vbuf(512) = 9216 floats (36KB)
    //       gemm uses As[64][36] + Bs[64][36] = 4608 floats
    __shared__ float pool[9216];
    __shared__ float colAcc[32];
    __shared__ float sstat[2][2][3][4];     // [sub][row][stat][warp]
    __shared__ int   soff[65];

    const int nPosB = n_pos >> 2;           // 256 blocks x 4 pos rows
    const int nColB = n_col >> 2;           // 128 blocks x 4 col rows
    const int prepB = nPosB + nColB;        // 384

    // ===================== phase A =====================
    if (bid < prepB) {
        const int sub = tid >> 7;           // 0,1
        const int h   = tid & 127;
        const bool isCol = (bid >= nPosB);
        const int r0blk = (isCol ? bid - nPosB : bid) * 4;
        const int r0 = r0blk + sub * 2;     // 2 rows per sub
        const float* feat = (isCol ? colf : seqf) + (size_t)r0 * D;
        const float* W1   = isCol ? Wc : Ws;
        const float* b1   = isCol ? bc : bs;

        float* sW   = pool;                  // [64][128] k-chunk of weights
        float* fbuf = pool + 8192;           // [4][128]
        float* vbuf = pool + 8192 + 512;     // [4][128]

        const int rr = sub * 2;
        fbuf[(rr + 0) * 128 + h] = feat[0 * D + h];
        fbuf[(rr + 1) * 128 + h] = feat[1 * D + h];
        __syncthreads();

        float acc0, acc1;
        {
            float bb = b1[h];
            acc0 = bb; acc1 = bb;
        }
        // ---- layer 1: two 64-k chunks, W staged in smem ----
        #pragma unroll
        for (int c = 0; c < 2; c++) {
            #pragma unroll
            for (int j = 0; j < 8; j++) {                 // 2048 float4 = [64][128]
                int i = tid + j * 256;
                int k = i >> 5, c4 = i & 31;
                *(float4*)&sW[k * 128 + c4 * 4] =
                    *(const float4*)&W1[(c * 64 + k) * H + c4 * 4];
            }
            __syncthreads();
            #pragma unroll 4
            for (int k4 = 0; k4 < 16; k4++) {
                float4 a0 = *(const float4*)&fbuf[(rr + 0) * 128 + c * 64 + k4 * 4];
                float4 a1 = *(const float4*)&fbuf[(rr + 1) * 128 + c * 64 + k4 * 4];
                #pragma unroll
                for (int kk = 0; kk < 4; kk++) {
                    float w = sW[(k4 * 4 + kk) * 128 + h];
                    float f0 = (kk == 0) ? a0.x : (kk == 1) ? a0.y : (kk == 2) ? a0.z : a0.w;
                    float f1 = (kk == 0) ? a1.x : (kk == 1) ? a1.y : (kk == 2) ? a1.z : a1.w;
                    acc0 = fmaf(f0, w, acc0);
                    acc1 = fmaf(f1, w, acc1);
                }
            }
            __syncthreads();
        }
        vbuf[(rr + 0) * 128 + h] = fmaxf(acc0, 0.f);
        vbuf[(rr + 1) * 128 + h] = fmaxf(acc1, 0.f);
        __syncthreads();

        // ---- layer 2 (Wm) ----
        {
            float bb = isCol ? bm[h] : 0.f;
            acc0 = bb; acc1 = bb;
        }
        #pragma unroll
        for (int c = 0; c < 2; c++) {
            #pragma unroll
            for (int j = 0; j < 8; j++) {                 // 2048 float4 = [64][128]
                int i = tid + j * 256;
                int k = i >> 5, c4 = i & 31;
                *(float4*)&sW[k * 128 + c4 * 4] =
                    *(const float4*)&Wm[(c * 64 + k) * H + c4 * 4];
            }
            __syncthreads();
            #pragma unroll 4
            for (int k4 = 0; k4 < 16; k4++) {
                float4 a0 = *(const float4*)&vbuf[(rr + 0) * 128 + c * 64 + k4 * 4];
                float4 a1 = *(const float4*)&vbuf[(rr + 1) * 128 + c * 64 + k4 * 4];
                #pragma unroll
                for (int kk = 0; kk < 4; kk++) {
                    float w = sW[(k4 * 4 + kk) * 128 + h];
                    float f0 = (kk == 0) ? a0.x : (kk == 1) ? a0.y : (kk == 2) ? a0.z : a0.w;
                    float f1 = (kk == 0) ? a1.x : (kk == 1) ? a1.y : (kk == 2) ? a1.z : a1.w;
                    acc0 = fmaf(f0, w, acc0);
                    acc1 = fmaf(f1, w, acc1);
                }
            }
            __syncthreads();
        }

        // ---- transposed store + per-row stats ----
        const float gh = gamma[h] * Wo[h];
        float* dT = isCol ? g_dBT : g_dAT;
        const int stride = isCol ? n_col : n_pos;
        #pragma unroll
        for (int r = 0; r < 2; r++) {
            float u = r ? acc1 : acc0;
            dT[(size_t)h * stride + r0 + r] = u;
            float a = u, b2 = u * u, cg = u * gh;
            #pragma unroll
            for (int o = 16; o > 0; o >>= 1) {
                a  += __shfl_down_sync(0xFFFFFFFFu, a,  o);
                b2 += __shfl_down_sync(0xFFFFFFFFu, b2, o);
                cg += __shfl_down_sync(0xFFFFFFFFu, cg, o);
            }
            if ((h & 31) == 0) {
                sstat[sub][r][0][h >> 5] = a;
                sstat[sub][r][1][h >> 5] = b2;
                sstat[sub][r][2][h >> 5] = cg;
            }
        }
        __syncthreads();
        if (h < 2) {
            int r = h;
            float4 st;
            st.x = sstat[sub][r][0][0] + sstat[sub][r][0][1] + sstat[sub][r][0][2] + sstat[sub][r][0][3];
            st.y = sstat[sub][r][1][0] + sstat[sub][r][1][1] + sstat[sub][r][1][2] + sstat[sub][r][1][3];
            st.z = sstat[sub][r][2][0] + sstat[sub][r][2][1] + sstat[sub][r][2][2] + sstat[sub][r][2][3];
            st.w = 0.f;
            if (isCol) g_cStat[r0 + r] = st; else g_rStat[r0 + r] = st;
        }
    } else {
        // ---- aux blocks: zero accumulators; first aux block does scalars + segIds ----
        const int hb = bid - prepB;
        const int nHelp = nblk - prepB;
        int total = n_pos + n_seq * n_col;
        for (int i = hb * 256 + tid; i < total; i += nHelp * 256) {
            if (i < n_pos) g_rowSum[i] = 0.f;
            else           g_segSum[i - n_pos] = 0.f;
        }
        if (hb == 0) {
            if (tid < 128) {
                float a = gamma[tid] * Wo[tid];
                float b = beta[tid] * Wo[tid];
                #pragma unroll
                for (int o = 16; o > 0; o >>= 1) {
                    a += __shfl_down_sync(0xFFFFFFFFu, a, o);
                    b += __shfl_down_sync(0xFFFFFFFFu, b, o);
                }
                if ((tid & 31) == 0) { colAcc[tid >> 5] = a; colAcc[4 + (tid >> 5)] = b; }
            }
            __syncthreads();
            if (tid == 0) {
                g_G  = colAcc[0] + colAcc[1] + colAcc[2] + colAcc[3];
                g_C0 = colAcc[4] + colAcc[5] + colAcc[6] + colAcc[7] + bo[0];
                int a2 = 0;
                for (int s = 0; s < n_seq; s++) { soff[s] = a2; a2 += lens[s]; }
                soff[n_seq] = a2;
            }
            __syncthreads();
            for (int p = tid; p < n_pos; p += 256) {
                int s = 0;
                while (s + 1 < n_seq && p >= soff[s + 1]) s++;
                g_segId[p] = s;
            }
        }
    }

    grid_barrier(nblk);

    // ===================== phase B : GEMM (32x32 tile, one per block) =====================
    const int nTN = n_col >> 5;                 // 16
    const int bx = bid & (nTN - 1), by = bid / nTN;
    const int m0 = by * 32, n0 = bx * 32;
    const int tx = tid & 15, ty = tid >> 4;     // 16 x 16 thread grid, 2x2 micro

    float (*As)[36] = (float(*)[36])pool;
    float (*Bs)[36] = (float(*)[36])(pool + 64 * 36);

    float acc00 = 0.f, acc01 = 0.f, acc10 = 0.f, acc11 = 0.f;

    #pragma unroll
    for (int kc = 0; kc < H; kc += 64) {
        #pragma unroll
        for (int j = 0; j < 2; j++) {
            int i = tid + j * 256;
            int k = i >> 3, c4 = i & 7;
            *(float4*)&As[k][c4 * 4] = *(const float4*)&g_dAT[(size_t)(kc + k) * n_pos + m0 + c4 * 4];
            *(float4*)&Bs[k][c4 * 4] = *(const float4*)&g_dBT[(size_t)(kc + k) * n_col + n0 + c4 * 4];
        }
        __syncthreads();
        #pragma unroll 8
        for (int k = 0; k < 64; k++) {
            float2 a = *(const float2*)&As[k][ty * 2];
            float2 b = *(const float2*)&Bs[k][tx * 2];
            acc00 = fmaf(a.x, b.x, acc00); acc01 = fmaf(a.x, b.y, acc01);
            acc10 = fmaf(a.y, b.x, acc10); acc11 = fmaf(a.y, b.y, acc11);
        }
        __syncthreads();
    }

    // ---- epilogue: LN closed form + exp + fused sums ----
    const float G = g_G, C0 = g_C0;
    const int mrow0 = m0 + ty * 2;
    const int ncol0 = n0 + tx * 2;
    float4 rs0 = g_rStat[mrow0], rs1 = g_rStat[mrow0 + 1];
    float4 cs0 = g_cStat[ncol0], cs1 = g_cStat[ncol0 + 1];

    float e[2][2];
    {
        float dots[2][2] = {{acc00, acc01}, {acc10, acc11}};
        #pragma unroll
        for (int i = 0; i < 2; i++) {
            float4 rs = i ? rs1 : rs0;
            #pragma unroll
            for (int j = 0; j < 2; j++) {
                float4 cs = j ? cs1 : cs0;
                float mu = (rs.x + cs.x) * (1.0f / H);
                float var = (rs.y + 2.f * dots[i][j] + cs.y) * (1.0f / H) - mu * mu;
                float inv = rsqrtf(var + LN_EPS);
                float raw = fmaf(rs.z + cs.z - mu * G, inv, C0);
                e[i][j] = __expf(raw);
            }
        }
    }

    // row sums: reduce across the 16 tx lanes (contiguous within warp half)
    #pragma unroll
    for (int i = 0; i < 2; i++) {
        float v = e[i][0] + e[i][1];
        #pragma unroll
        for (int o = 8; o > 0; o >>= 1) v += __shfl_down_sync(0xFFFFFFFFu, v, o, 16);
        if (tx == 0) atomicAdd(&g_rowSum[mrow0 + i], v);
    }

    // column/segment sums
    float cp0 = e[0][0] + e[1][0];
    float cp1 = e[0][1] + e[1][1];
    cp0 += __shfl_down_sync(0xFFFFFFFFu, cp0, 16);   // combine the warp's two ty rows
    cp1 += __shfl_down_sync(0xFFFFFFFFu, cp1, 16);

    const int s0 = g_segId[mrow0], s1 = g_segId[mrow0 + 1];
    const int sA = g_segId[m0], sB = g_segId[m0 + 31];
    if (sA == sB) {
        if (tid < 32) colAcc[tid] = 0.f;
        __syncthreads();
        if ((tid & 31) < 16) {
            atomicAdd(&colAcc[tx * 2 + 0], cp0);
            atomicAdd(&colAcc[tx * 2 + 1], cp1);
        }
        __syncthreads();
        if (tid < 32) atomicAdd(&g_segSum[sA * n_col + n0 + tid], colAcc[tid]);
    } else {
        #pragma unroll
        for (int i = 0; i < 2; i++) {
            int s = i ? s1 : s0;
            atomicAdd(&g_segSum[s * n_col + ncol0 + 0], e[i][0]);
            atomicAdd(&g_segSum[s * n_col + ncol0 + 1], e[i][1]);
        }
    }

    grid_barrier(nblk);

    // ---- finalize: Mc + Ms - Mc*Ms ----
    #pragma unroll
    for (int i = 0; i < 2; i++) {
        int m = mrow0 + i;
        float Rinv = __frcp_rn(g_rowSum[m]);
        int s = i ? s1 : s0;
        const float2 ss = *(const float2*)&g_segSum[s * n_col + ncol0];
        float mc0 = e[i][0] * Rinv, ms0 = e[i][0] * __frcp_rn(ss.x);
        float mc1 = e[i][1] * Rinv, ms1 = e[i][1] * __frcp_rn(ss.y);
        float2 o;
        o.x = mc0 + ms0 - mc0 * ms0;
        o.y = mc1 + ms1 - mc1 * ms1;
        *(float2*)&E[(size_t)m * n_col + ncol0] = o;
    }
}

// ---------------- host launcher ----------------
extern "C" void kernel_launch(void* const* d_in, const int* in_sizes, int n_in,
                              void* d_out, int out_size) {
    const float* seqf  = (const float*)d_in[0];
    const float* colf  = (const float*)d_in[1];
    const int*   lens  = (const int*)  d_in[2];
    const float* Ws    = (const float*)d_in[3];
    const float* bs    = (const float*)d_in[4];
    const float* Wc    = (const float*)d_in[5];
    const float* bc    = (const float*)d_in[6];
    const float* Wm    = (const float*)d_in[7];
    const float* bm    = (const float*)d_in[8];
    const float* gamma = (const float*)d_in[9];
    const float* beta  = (const float*)d_in[10];
    const float* Wo    = (const float*)d_in[11];
    const float* bo    = (const float*)d_in[12];

    int n_seq = in_sizes[2];
    int n_pos = in_sizes[0] / D;   // 1024
    int n_col = in_sizes[1] / D;   // 512
    float* E = (float*)d_out;

    int nblk = (n_pos / 32) * (n_col / 32);   // 512 blocks, 4/SM resident (cap 592)
    k_fused<<<nblk, 256>>>(seqf, colf, Ws, bs, Wc, bc, Wm, bm,
                           gamma, beta, Wo, bo, lens, E,
                           n_pos, n_col, n_seq, nblk);
}